// round 10
// baseline (speedup 1.0000x reference)
#include <cuda_runtime.h>
#include <cuda_fp16.h>
#include <cstdint>
#include <cstddef>
#include <math.h>

// ----------------------------------------------------------------------------
// Problem dims
// ----------------------------------------------------------------------------
#define TOKENS 8192
#define INF    4096
#define OUTF   16384

// GEMM tile config: 128x256 CTA, 8 warps of 64x64, 4-stage pipeline
#define BM 128
#define BN 256
#define BK 64                        // fp16 elems per k-chunk = 128 bytes/row
#define NIT (INF / BK)               // 64 iterations
#define A_TILE_BYTES (BM * 128)      // 16384
#define B_TILE_BYTES (BN * 128)      // 32768
#define STAGE_BYTES (A_TILE_BYTES + B_TILE_BYTES)   // 49152
#define NSTAGE 4
#define SMEM_TOTAL (NSTAGE * STAGE_BYTES)           // 196608 (<= 227KB max)

// ----------------------------------------------------------------------------
// Scratch (device globals: allocation-free rule)
// ----------------------------------------------------------------------------
__device__ __align__(128) __half g_Wh[(size_t)OUTF   * INF];
__device__ __align__(128) __half g_Ah[(size_t)TOKENS * INF];
__device__ int g_swap;   // 1 if small0 is actually bias (scale is strictly positive)
__device__ int g_wfmt;   // weight marshaling: 0=int8 raw, 1=int32, 2=float32

// ----------------------------------------------------------------------------
// PTX helpers
// ----------------------------------------------------------------------------
__device__ __forceinline__ void cp_async16(void* dst, const void* src) {
    uint32_t d;
    asm("{ .reg .u64 t; cvta.to.shared.u64 t, %1; cvt.u32.u64 %0, t; }" : "=r"(d) : "l"(dst));
    asm volatile("cp.async.cg.shared.global [%0], [%1], 16;" :: "r"(d), "l"(src) : "memory");
}

__device__ __forceinline__ void ldm4(uint32_t r[4], uint32_t addr) {
    asm volatile("ldmatrix.sync.aligned.m8n8.x4.shared.b16 {%0,%1,%2,%3}, [%4];"
                 : "=r"(r[0]), "=r"(r[1]), "=r"(r[2]), "=r"(r[3])
                 : "r"(addr) : "memory");
}

__device__ __forceinline__ uint32_t smem_u32(const void* p) {
    uint32_t a;
    asm("{ .reg .u64 t; cvta.to.shared.u64 t, %1; cvt.u32.u64 %0, t; }"
        : "=r"(a) : "l"(p));
    return a;
}

__device__ __forceinline__ void mma16816(float c[4], uint32_t a0, uint32_t a1,
                                         uint32_t a2, uint32_t a3,
                                         uint32_t b0, uint32_t b1) {
    asm volatile(
        "mma.sync.aligned.m16n8k16.row.col.f32.f16.f16.f32 "
        "{%0,%1,%2,%3}, {%4,%5,%6,%7}, {%8,%9}, {%0,%1,%2,%3};"
        : "+f"(c[0]), "+f"(c[1]), "+f"(c[2]), "+f"(c[3])
        : "r"(a0), "r"(a1), "r"(a2), "r"(a3), "r"(b0), "r"(b1));
}

// ----------------------------------------------------------------------------
// Prepass 0a: detect weight marshaling (int32 on this harness; kept for safety)
// ----------------------------------------------------------------------------
__global__ void detect_wfmt_kernel(const void* __restrict__ w) {
    const int32_t* wi = (const int32_t*)w;
    const float*   wf = (const float*)w;
    __shared__ int not_i32, not_f32;
    if (threadIdx.x == 0) { not_i32 = 0; not_f32 = 0; }
    __syncthreads();
    for (int i = threadIdx.x; i < 16384; i += blockDim.x) {
        int v = wi[i];
        if (v < -127 || v > 127) not_i32 = 1;            // benign race, idempotent
        float f = wf[i];
        if (!(f == rintf(f) && fabsf(f) <= 127.0f)) not_f32 = 1;
    }
    __syncthreads();
    if (threadIdx.x == 0) g_wfmt = (!not_i32) ? 1 : ((!not_f32) ? 2 : 0);
}

// ----------------------------------------------------------------------------
// Prepass 0b: identify scale vs bias (scale strictly positive; bias has negatives)
// ----------------------------------------------------------------------------
__global__ void detect_kernel(const float* __restrict__ c0, const float* __restrict__ c1) {
    __shared__ int neg0, neg1;
    if (threadIdx.x == 0) { neg0 = 0; neg1 = 0; }
    __syncthreads();
    for (int i = threadIdx.x; i < OUTF; i += blockDim.x) {
        if (c0[i] < 0.0f) neg0 = 1;   // benign race, idempotent
        if (c1[i] < 0.0f) neg1 = 1;
    }
    __syncthreads();
    if (threadIdx.x == 0) g_swap = (neg0 && !neg1) ? 1 : 0;
}

// ----------------------------------------------------------------------------
// Prepass 1: weight (int8 / int32 / float32 marshaled) -> exact fp16
// ----------------------------------------------------------------------------
__global__ void __launch_bounds__(256) convert_w_kernel(const void* __restrict__ wraw) {
    size_t i = (size_t)blockIdx.x * blockDim.x + threadIdx.x;
    size_t base = i * 8;
    int fmt = g_wfmt;
    float f[8];
    if (fmt == 1) {
        const int4* p = (const int4*)((const int32_t*)wraw + base);
        int4 a = p[0], b = p[1];
        f[0] = (float)a.x; f[1] = (float)a.y; f[2] = (float)a.z; f[3] = (float)a.w;
        f[4] = (float)b.x; f[5] = (float)b.y; f[6] = (float)b.z; f[7] = (float)b.w;
    } else if (fmt == 2) {
        const float4* p = (const float4*)((const float*)wraw + base);
        float4 a = p[0], b = p[1];
        f[0] = a.x; f[1] = a.y; f[2] = a.z; f[3] = a.w;
        f[4] = b.x; f[5] = b.y; f[6] = b.z; f[7] = b.w;
    } else {
        long long v = *(const long long*)((const int8_t*)wraw + base);
#pragma unroll
        for (int j = 0; j < 8; j++)
            f[j] = (float)(int)(signed char)((v >> (8 * j)) & 0xFF);
    }
    __half o[8];
#pragma unroll
    for (int j = 0; j < 8; j++) o[j] = __float2half_rn(f[j]);   // exact: |w|<=127
    *(uint4*)(&g_Wh[base]) = *(const uint4*)o;
}

// ----------------------------------------------------------------------------
// Prepass 2: fp32 input -> fp16
// ----------------------------------------------------------------------------
__global__ void __launch_bounds__(256) convert_a_kernel(const float* __restrict__ x) {
    size_t i = (size_t)blockIdx.x * blockDim.x + threadIdx.x;
    size_t base = i * 8;
    float4 v0 = *(const float4*)(x + base);
    float4 v1 = *(const float4*)(x + base + 4);
    __half o[8];
    o[0] = __float2half_rn(v0.x); o[1] = __float2half_rn(v0.y);
    o[2] = __float2half_rn(v0.z); o[3] = __float2half_rn(v0.w);
    o[4] = __float2half_rn(v1.x); o[5] = __float2half_rn(v1.y);
    o[6] = __float2half_rn(v1.z); o[7] = __float2half_rn(v1.w);
    *(uint4*)(&g_Ah[base]) = *(const uint4*)o;
}

// ----------------------------------------------------------------------------
// Main GEMM: 128x256 CTA, 256 threads, 8 warps of 64x64, 4-stage cp.async.
// ----------------------------------------------------------------------------
__global__ void __launch_bounds__(256, 1) gemm_kernel(
    float* __restrict__ out,
    const float* __restrict__ small0,   // scale or bias (see g_swap)
    const float* __restrict__ small1)
{
    extern __shared__ __align__(1024) char smem[];
    const int tid = threadIdx.x;
    const int wid = tid >> 5;
    const int lane = tid & 31;
    const uint32_t sbase = smem_u32(smem);

    // Raster: MT=64, NT=64; GROUP_M=16 -> W streamed 4x
    const int NT = OUTF / BN;            // 64
    int t = blockIdx.x;
    int grp = t / (16 * NT);
    int rem = t % (16 * NT);
    int mt = grp * 16 + (rem % 16);
    int nt = rem / 16;
    const int m0 = mt * BM;
    const int n0 = nt * BN;

    // warp layout: 2 (M) x 4 (N); warp tile 64 x 64
    const int warp_m = (wid & 1) * 64;
    const int warp_n = (wid >> 1) * 64;
    const int tr = lane & 15;            // ldmatrix row-within-16
    const int th = lane >> 4;            // ldmatrix 16B-half select

    // ldmatrix row bases + swizzle XOR keys (phys = row*128 + (cb ^ ((row&7)<<4)))
    uint32_t a_row[4], a_or[4], b_row[4], b_or[4];
#pragma unroll
    for (int f = 0; f < 4; f++) {
        int r = warp_m + f * 16 + tr;
        a_row[f] = r * 128;
        a_or[f] = (r & 7) << 4;
    }
#pragma unroll
    for (int g = 0; g < 4; g++) {
        int r = warp_n + g * 16 + tr;
        b_row[g] = r * 128;
        b_or[g] = (r & 7) << 4;
    }

    // ---- global load bases ----
    const char* gA = (const char*)g_Ah + (size_t)m0 * (INF * 2);
    const char* gW = (const char*)g_Wh + (size_t)n0 * (INF * 2);

    // producer mapping: A 1024 granules (4/thread), B 2048 granules (8/thread)
    uint32_t ldA_dst[4], ldA_src[4], ldB_dst[8], ldB_src[8];
#pragma unroll
    for (int j = 0; j < 4; j++) {
        int idx = j * 256 + tid;
        int row = idx >> 3;
        int cb = (idx & 7) * 16;
        ldA_dst[j] = row * 128 + (cb ^ ((row & 7) << 4));
        ldA_src[j] = row * (INF * 2) + cb;
    }
#pragma unroll
    for (int j = 0; j < 8; j++) {
        int idx = j * 256 + tid;
        int row = idx >> 3;
        int cb = (idx & 7) * 16;
        ldB_dst[j] = row * 128 + (cb ^ ((row & 7) << 4));
        ldB_src[j] = row * (INF * 2) + cb;
    }

    auto load_stage = [&](int stage, int ki) {
        char* st = smem + stage * STAGE_BYTES;
        uint32_t koff = ki * 128;
#pragma unroll
        for (int j = 0; j < 4; j++)
            cp_async16(st + ldA_dst[j], gA + ldA_src[j] + koff);
#pragma unroll
        for (int j = 0; j < 8; j++)
            cp_async16(st + A_TILE_BYTES + ldB_dst[j], gW + ldB_src[j] + koff);
        asm volatile("cp.async.commit_group;" ::: "memory");
    };

    float acc[4][8][4];
#pragma unroll
    for (int f = 0; f < 4; f++)
#pragma unroll
        for (int nf = 0; nf < 8; nf++)
#pragma unroll
            for (int k = 0; k < 4; k++) acc[f][nf][k] = 0.0f;

    load_stage(0, 0);
    load_stage(1, 1);
    load_stage(2, 2);

    int s = 0;
    for (int i = 0; i < NIT; i++) {
        asm volatile("cp.async.wait_group 2;" ::: "memory");   // group i complete
        __syncthreads();   // all warps done reading stage (i-1)%4, now overwritten

        if (i + 3 < NIT)
            load_stage((s + 3) & 3, i + 3);

        uint32_t sA = sbase + s * STAGE_BYTES;
        uint32_t sB = sA + A_TILE_BYTES;

#pragma unroll
        for (int ks = 0; ks < 4; ks++) {
            uint32_t c0 = ks * 32 + th * 16;

            uint32_t rb[4][4];
#pragma unroll
            for (int g = 0; g < 4; g++)
                ldm4(rb[g], sB + b_row[g] + (c0 ^ b_or[g]));

            uint32_t ra[4][4];
#pragma unroll
            for (int f = 0; f < 4; f++)
                ldm4(ra[f], sA + a_row[f] + (c0 ^ a_or[f]));

#pragma unroll
            for (int f = 0; f < 4; f++)
#pragma unroll
                for (int g = 0; g < 4; g++) {
                    mma16816(acc[f][g * 2 + 0], ra[f][0], ra[f][1], ra[f][2], ra[f][3],
                             rb[g][0], rb[g][2]);
                    mma16816(acc[f][g * 2 + 1], ra[f][0], ra[f][1], ra[f][2], ra[f][3],
                             rb[g][1], rb[g][3]);
                }
        }

        s = (s + 1) & 3;
    }
    __syncthreads();

    // ---- epilogue: out = acc * scale[n] + bias[n] ----
    const float* scp = g_swap ? small1 : small0;
    const float* bip = g_swap ? small0 : small1;

    float* s_sc = (float*)smem;
    float* s_bi = s_sc + BN;
    for (int j = tid; j < BN; j += 256) {
        s_sc[j] = scp[n0 + j];
        s_bi[j] = bip[n0 + j];
    }
    __syncthreads();

#pragma unroll
    for (int f = 0; f < 4; f++) {
#pragma unroll
        for (int nf = 0; nf < 8; nf++) {
            int col = warp_n + nf * 8 + 2 * (lane & 3);
            float sc0 = s_sc[col], sc1 = s_sc[col + 1];
            float bi0 = s_bi[col], bi1 = s_bi[col + 1];
#pragma unroll
            for (int h = 0; h < 2; h++) {
                int row = m0 + warp_m + f * 16 + (lane >> 2) + h * 8;
                float2 v;
                v.x = acc[f][nf][2 * h + 0] * sc0 + bi0;
                v.y = acc[f][nf][2 * h + 1] * sc1 + bi1;
                *(float2*)(out + (size_t)row * OUTF + n0 + col) = v;
            }
        }
    }
}

// ----------------------------------------------------------------------------
// Launch: identify inputs by element count (robust to metadata ordering)
// ----------------------------------------------------------------------------
extern "C" void kernel_launch(void* const* d_in, const int* in_sizes, int n_in,
                              void* d_out, int out_size) {
    const float* inp = nullptr;
    const void*  w   = nullptr;
    const float* small0 = nullptr;
    const float* small1 = nullptr;

    for (int i = 0; i < n_in; i++) {
        if (in_sizes[i] == TOKENS * INF)      inp = (const float*)d_in[i];
        else if (in_sizes[i] == OUTF * INF)   w   = d_in[i];
        else if (!small0)                     small0 = (const float*)d_in[i];
        else                                  small1 = (const float*)d_in[i];
    }
    float* out = (float*)d_out;

    cudaFuncSetAttribute(gemm_kernel, cudaFuncAttributeMaxDynamicSharedMemorySize, SMEM_TOTAL);

    detect_wfmt_kernel<<<1, 256>>>(w);
    detect_kernel<<<1, 256>>>(small0, small1);

    size_t n_w = (size_t)OUTF * INF / 8;
    convert_w_kernel<<<(unsigned)(n_w / 256), 256>>>(w);
    size_t n_a = (size_t)TOKENS * INF / 8;
    convert_a_kernel<<<(unsigned)(n_a / 256), 256>>>(inp);

    // 64 x 64 tiles = 4096 CTAs
    gemm_kernel<<<4096, 256, SMEM_TOTAL>>>(out, small0, small1);
}

// round 11
// speedup vs baseline: 1.2010x; 1.2010x over previous
#include <cuda_runtime.h>
#include <cuda_fp16.h>
#include <cuda.h>
#include <cstdint>
#include <cstddef>
#include <math.h>

// ----------------------------------------------------------------------------
// Problem dims
// ----------------------------------------------------------------------------
#define TOKENS 8192
#define INF    4096
#define OUTF   16384

// GEMM tile config: 128x128 CTA, 8 warps of 32x64, 3-stage TMA pipeline
#define BM 128
#define BN 128
#define BK 64                        // fp16 elems per k-chunk = 128 bytes/row
#define NIT (INF / BK)               // 64 iterations
#define A_TILE_BYTES (BM * 128)      // 16384
#define STAGE_BYTES (2 * A_TILE_BYTES)  // A + W = 32768
#define NSTAGE 3
#define SMEM_DATA_OFF 1024           // mbarriers live below
#define SMEM_TOTAL (SMEM_DATA_OFF + NSTAGE * STAGE_BYTES)   // 99328 -> 2 CTAs/SM

// ----------------------------------------------------------------------------
// Scratch (device globals: allocation-free rule)
// ----------------------------------------------------------------------------
__device__ __align__(128) __half g_Wh[(size_t)OUTF   * INF];
__device__ __align__(128) __half g_Ah[(size_t)TOKENS * INF];
__device__ int g_swap;   // 1 if small0 is actually bias (scale is strictly positive)
__device__ int g_wfmt;   // weight marshaling: 0=int8 raw, 1=int32, 2=float32

// ----------------------------------------------------------------------------
// PTX helpers
// ----------------------------------------------------------------------------
__device__ __forceinline__ void ldm4(uint32_t r[4], uint32_t addr) {
    asm volatile("ldmatrix.sync.aligned.m8n8.x4.shared.b16 {%0,%1,%2,%3}, [%4];"
                 : "=r"(r[0]), "=r"(r[1]), "=r"(r[2]), "=r"(r[3])
                 : "r"(addr) : "memory");
}

__device__ __forceinline__ uint32_t smem_u32(const void* p) {
    uint32_t a;
    asm("{ .reg .u64 t; cvta.to.shared.u64 t, %1; cvt.u32.u64 %0, t; }"
        : "=r"(a) : "l"(p));
    return a;
}

__device__ __forceinline__ void mma16816(float c[4], uint32_t a0, uint32_t a1,
                                         uint32_t a2, uint32_t a3,
                                         uint32_t b0, uint32_t b1) {
    asm volatile(
        "mma.sync.aligned.m16n8k16.row.col.f32.f16.f16.f32 "
        "{%0,%1,%2,%3}, {%4,%5,%6,%7}, {%8,%9}, {%0,%1,%2,%3};"
        : "+f"(c[0]), "+f"(c[1]), "+f"(c[2]), "+f"(c[3])
        : "r"(a0), "r"(a1), "r"(a2), "r"(a3), "r"(b0), "r"(b1));
}

#define MBARRIER_INIT(addr, cnt) \
    asm volatile("mbarrier.init.shared.b64 [%0], %1;" :: "r"((uint32_t)(addr)), "r"((uint32_t)(cnt)) : "memory")

#define MBARRIER_EXPECT_TX(addr, tx) \
    asm volatile("mbarrier.arrive.expect_tx.shared.b64 _, [%0], %1;" :: "r"((uint32_t)(addr)), "r"((uint32_t)(tx)) : "memory")

#define MBARRIER_WAIT_PARITY(mbar_smem_addr, phase_parity) do {                              \
    uint32_t _mbar = (uint32_t)(mbar_smem_addr);                                             \
    uint32_t _parity = (uint32_t)(phase_parity);                                             \
    uint32_t _done;                                                                          \
    asm volatile("{\n\t.reg .pred p;\n\t"                                                    \
        "mbarrier.try_wait.parity.acquire.cta.shared::cta.b64 p, [%1], %2;\n\t"              \
        "selp.b32 %0, 1, 0, p;\n\t}"                                                         \
        : "=r"(_done) : "r"(_mbar), "r"(_parity) : "memory");                                \
    if (!_done) {                                                                            \
        asm volatile("{\n\t.reg .pred P1;\n\t"                                               \
            "WAIT_LOOP_%=:\n\t"                                                              \
            "mbarrier.try_wait.parity.acquire.cta.shared::cta.b64 P1, [%0], %1, 0x989680;\n\t" \
            "@P1 bra.uni WAIT_DONE_%=;\n\t"                                                  \
            "bra.uni WAIT_LOOP_%=;\n\t"                                                      \
            "WAIT_DONE_%=:\n\t}"                                                             \
            :: "r"(_mbar), "r"(_parity) : "memory");                                         \
    }                                                                                        \
} while (0)

__device__ __forceinline__ void tma_load_2d(uint32_t dst, const CUtensorMap* tm,
                                            int x, int y, uint32_t mbar) {
    asm volatile(
        "cp.async.bulk.tensor.2d.shared::cta.global.tile.mbarrier::complete_tx::bytes "
        "[%0], [%1, {%2, %3}], [%4];"
        :: "r"(dst), "l"(tm), "r"(x), "r"(y), "r"(mbar) : "memory");
}

// ----------------------------------------------------------------------------
// Prepass 0a: detect weight marshaling (int32 on this harness; kept for safety)
// ----------------------------------------------------------------------------
__global__ void detect_wfmt_kernel(const void* __restrict__ w) {
    const int32_t* wi = (const int32_t*)w;
    const float*   wf = (const float*)w;
    __shared__ int not_i32, not_f32;
    if (threadIdx.x == 0) { not_i32 = 0; not_f32 = 0; }
    __syncthreads();
    for (int i = threadIdx.x; i < 16384; i += blockDim.x) {
        int v = wi[i];
        if (v < -127 || v > 127) not_i32 = 1;            // benign race, idempotent
        float f = wf[i];
        if (!(f == rintf(f) && fabsf(f) <= 127.0f)) not_f32 = 1;
    }
    __syncthreads();
    if (threadIdx.x == 0) g_wfmt = (!not_i32) ? 1 : ((!not_f32) ? 2 : 0);
}

// ----------------------------------------------------------------------------
// Prepass 0b: identify scale vs bias (scale strictly positive; bias has negatives)
// ----------------------------------------------------------------------------
__global__ void detect_kernel(const float* __restrict__ c0, const float* __restrict__ c1) {
    __shared__ int neg0, neg1;
    if (threadIdx.x == 0) { neg0 = 0; neg1 = 0; }
    __syncthreads();
    for (int i = threadIdx.x; i < OUTF; i += blockDim.x) {
        if (c0[i] < 0.0f) neg0 = 1;   // benign race, idempotent
        if (c1[i] < 0.0f) neg1 = 1;
    }
    __syncthreads();
    if (threadIdx.x == 0) g_swap = (neg0 && !neg1) ? 1 : 0;
}

// ----------------------------------------------------------------------------
// Prepass 1: weight (int8 / int32 / float32 marshaled) -> exact fp16
// ----------------------------------------------------------------------------
__global__ void __launch_bounds__(256) convert_w_kernel(const void* __restrict__ wraw) {
    size_t i = (size_t)blockIdx.x * blockDim.x + threadIdx.x;
    size_t base = i * 8;
    int fmt = g_wfmt;
    float f[8];
    if (fmt == 1) {
        const int4* p = (const int4*)((const int32_t*)wraw + base);
        int4 a = p[0], b = p[1];
        f[0] = (float)a.x; f[1] = (float)a.y; f[2] = (float)a.z; f[3] = (float)a.w;
        f[4] = (float)b.x; f[5] = (float)b.y; f[6] = (float)b.z; f[7] = (float)b.w;
    } else if (fmt == 2) {
        const float4* p = (const float4*)((const float*)wraw + base);
        float4 a = p[0], b = p[1];
        f[0] = a.x; f[1] = a.y; f[2] = a.z; f[3] = a.w;
        f[4] = b.x; f[5] = b.y; f[6] = b.z; f[7] = b.w;
    } else {
        long long v = *(const long long*)((const int8_t*)wraw + base);
#pragma unroll
        for (int j = 0; j < 8; j++)
            f[j] = (float)(int)(signed char)((v >> (8 * j)) & 0xFF);
    }
    __half o[8];
#pragma unroll
    for (int j = 0; j < 8; j++) o[j] = __float2half_rn(f[j]);   // exact: |w|<=127
    *(uint4*)(&g_Wh[base]) = *(const uint4*)o;
}

// ----------------------------------------------------------------------------
// Prepass 2: fp32 input -> fp16
// ----------------------------------------------------------------------------
__global__ void __launch_bounds__(256) convert_a_kernel(const float* __restrict__ x) {
    size_t i = (size_t)blockIdx.x * blockDim.x + threadIdx.x;
    size_t base = i * 8;
    float4 v0 = *(const float4*)(x + base);
    float4 v1 = *(const float4*)(x + base + 4);
    __half o[8];
    o[0] = __float2half_rn(v0.x); o[1] = __float2half_rn(v0.y);
    o[2] = __float2half_rn(v0.z); o[3] = __float2half_rn(v0.w);
    o[4] = __float2half_rn(v1.x); o[5] = __float2half_rn(v1.y);
    o[6] = __float2half_rn(v1.z); o[7] = __float2half_rn(v1.w);
    *(uint4*)(&g_Ah[base]) = *(const uint4*)o;
}

// ----------------------------------------------------------------------------
// Main GEMM: 128x128 tile, 256 threads, 3-stage TMA pipeline, ldmatrix,
// single fp16 pass. TMA replaces 2048 LDGSTS/iter with 2 instructions.
// ----------------------------------------------------------------------------
__global__ void __launch_bounds__(256, 2) gemm_kernel(
    float* __restrict__ out,
    const float* __restrict__ small0,   // scale or bias (see g_swap)
    const float* __restrict__ small1,
    const __grid_constant__ CUtensorMap tmA,
    const __grid_constant__ CUtensorMap tmW)
{
    extern __shared__ __align__(1024) char smem[];
    const int tid = threadIdx.x;
    const int wid = tid >> 5;
    const int lane = tid & 31;
    const uint32_t sbase = smem_u32(smem);

    // Tile raster: GROUP_M=16 so weight tiles stream only 4x through DRAM
    const int NT = OUTF / BN;            // 128
    int t = blockIdx.x;
    int grp = t / (16 * NT);
    int rem = t % (16 * NT);
    int mt = grp * 16 + (rem % 16);
    int nt = rem / 16;
    const int m0 = mt * BM;
    const int n0 = nt * BN;

    // warp layout: 4 (M) x 2 (N); warp tile 32 x 64
    const int warp_m = (wid & 3) * 32;
    const int warp_n = (wid >> 2) * 64;
    const int tr = lane & 15;            // ldmatrix row-within-16
    const int th = lane >> 4;            // ldmatrix 16B-half select

    // ldmatrix row bases + swizzle XOR keys.
    // TMA SWIZZLE_128B produces phys = row*128 + (cb ^ ((row&7)<<4)) within a tile.
    uint32_t a_row[2], a_or[2], b_row[4], b_or[4];
#pragma unroll
    for (int f = 0; f < 2; f++) {
        int r = warp_m + f * 16 + tr;
        a_row[f] = r * 128;
        a_or[f] = (r & 7) << 4;
    }
#pragma unroll
    for (int g = 0; g < 4; g++) {
        int r = warp_n + g * 16 + tr;
        b_row[g] = r * 128;
        b_or[g] = (r & 7) << 4;
    }

    // mbarriers: one per stage at sbase + s*8
    if (tid == 0) {
#pragma unroll
        for (int s = 0; s < NSTAGE; s++) MBARRIER_INIT(sbase + s * 8, 1);
    }
    __syncthreads();

    // Prologue: fill all 3 stages
    if (tid == 0) {
#pragma unroll
        for (int s = 0; s < NSTAGE; s++) {
            uint32_t st = sbase + SMEM_DATA_OFF + s * STAGE_BYTES;
            MBARRIER_EXPECT_TX(sbase + s * 8, STAGE_BYTES);
            tma_load_2d(st,                &tmA, s * BK, m0, sbase + s * 8);
            tma_load_2d(st + A_TILE_BYTES, &tmW, s * BK, n0, sbase + s * 8);
        }
    }

    float acc[2][8][4];
#pragma unroll
    for (int f = 0; f < 2; f++)
#pragma unroll
        for (int nf = 0; nf < 8; nf++)
#pragma unroll
            for (int k = 0; k < 4; k++) acc[f][nf][k] = 0.0f;

    uint32_t par = 0;   // parity bit per stage
    int s = 0;
    for (int i = 0; i < NIT; i++) {
        MBARRIER_WAIT_PARITY(sbase + s * 8, (par >> s) & 1);

        uint32_t sA = sbase + SMEM_DATA_OFF + s * STAGE_BYTES;
        uint32_t sB = sA + A_TILE_BYTES;

#pragma unroll
        for (int ks = 0; ks < 4; ks++) {
            uint32_t c0 = ks * 32 + th * 16;

            uint32_t rb[4][4];
#pragma unroll
            for (int g = 0; g < 4; g++)
                ldm4(rb[g], sB + b_row[g] + (c0 ^ b_or[g]));

            uint32_t ra[2][4];
#pragma unroll
            for (int f = 0; f < 2; f++)
                ldm4(ra[f], sA + a_row[f] + (c0 ^ a_or[f]));

#pragma unroll
            for (int f = 0; f < 2; f++)
#pragma unroll
                for (int g = 0; g < 4; g++) {
                    mma16816(acc[f][g * 2 + 0], ra[f][0], ra[f][1], ra[f][2], ra[f][3],
                             rb[g][0], rb[g][2]);
                    mma16816(acc[f][g * 2 + 1], ra[f][0], ra[f][1], ra[f][2], ra[f][3],
                             rb[g][1], rb[g][3]);
                }
        }

        __syncthreads();   // all warps done reading stage s
        par ^= (1u << s);
        if (i + NSTAGE < NIT && tid == 0) {
            uint32_t st = sbase + SMEM_DATA_OFF + s * STAGE_BYTES;
            MBARRIER_EXPECT_TX(sbase + s * 8, STAGE_BYTES);
            tma_load_2d(st,                &tmA, (i + NSTAGE) * BK, m0, sbase + s * 8);
            tma_load_2d(st + A_TILE_BYTES, &tmW, (i + NSTAGE) * BK, n0, sbase + s * 8);
        }
        s = s + 1 >= NSTAGE ? 0 : s + 1;
    }

    // ---- epilogue: out = acc * scale[n] + bias[n] ----
    const float* scp = g_swap ? small1 : small0;
    const float* bip = g_swap ? small0 : small1;

    float* s_sc = (float*)(smem + SMEM_DATA_OFF);
    float* s_bi = s_sc + BN;
    for (int j = tid; j < BN; j += 256) {
        s_sc[j] = scp[n0 + j];
        s_bi[j] = bip[n0 + j];
    }
    __syncthreads();

#pragma unroll
    for (int f = 0; f < 2; f++) {
#pragma unroll
        for (int nf = 0; nf < 8; nf++) {
            int col = warp_n + nf * 8 + 2 * (lane & 3);
            float sc0 = s_sc[col], sc1 = s_sc[col + 1];
            float bi0 = s_bi[col], bi1 = s_bi[col + 1];
#pragma unroll
            for (int h = 0; h < 2; h++) {
                int row = m0 + warp_m + f * 16 + (lane >> 2) + h * 8;
                float2 v;
                v.x = acc[f][nf][2 * h + 0] * sc0 + bi0;
                v.y = acc[f][nf][2 * h + 1] * sc1 + bi1;
                *(float2*)(out + (size_t)row * OUTF + n0 + col) = v;
            }
        }
    }
}

// ----------------------------------------------------------------------------
// Host: tensor-map encode via runtime-resolved driver entry point (no -lcuda)
// ----------------------------------------------------------------------------
typedef CUresult (*PFN_encodeTiled)(
    CUtensorMap*, CUtensorMapDataType, cuuint32_t, void*,
    const cuuint64_t*, const cuuint64_t*, const cuuint32_t*, const cuuint32_t*,
    CUtensorMapInterleave, CUtensorMapSwizzle, CUtensorMapL2promotion,
    CUtensorMapFloatOOBfill);

static void encode_map(PFN_encodeTiled fn, CUtensorMap* tm, void* base,
                       unsigned long long rows) {
    cuuint64_t dims[2]    = {(cuuint64_t)INF, (cuuint64_t)rows};
    cuuint64_t strides[1] = {(cuuint64_t)INF * 2};
    cuuint32_t box[2]     = {BK, BM};          // 64 fp16 = 128B (SW128 limit), 128 rows
    cuuint32_t estr[2]    = {1, 1};
    fn(tm, CU_TENSOR_MAP_DATA_TYPE_FLOAT16, 2, base, dims, strides, box, estr,
       CU_TENSOR_MAP_INTERLEAVE_NONE, CU_TENSOR_MAP_SWIZZLE_128B,
       CU_TENSOR_MAP_L2_PROMOTION_L2_128B, CU_TENSOR_MAP_FLOAT_OOB_FILL_NONE);
}

extern "C" void kernel_launch(void* const* d_in, const int* in_sizes, int n_in,
                              void* d_out, int out_size) {
    const float* inp = nullptr;
    const void*  w   = nullptr;
    const float* small0 = nullptr;
    const float* small1 = nullptr;

    for (int i = 0; i < n_in; i++) {
        if (in_sizes[i] == TOKENS * INF)      inp = (const float*)d_in[i];
        else if (in_sizes[i] == OUTF * INF)   w   = d_in[i];
        else if (!small0)                     small0 = (const float*)d_in[i];
        else                                  small1 = (const float*)d_in[i];
    }
    float* out = (float*)d_out;

    // Resolve cuTensorMapEncodeTiled without linking libcuda
    PFN_encodeTiled encode_fn = nullptr;
#if CUDART_VERSION >= 12050
    {
        cudaDriverEntryPointQueryResult qr;
        cudaGetDriverEntryPointByVersion("cuTensorMapEncodeTiled",
                                         (void**)&encode_fn, 12000,
                                         cudaEnableDefault, &qr);
    }
#else
    cudaGetDriverEntryPoint("cuTensorMapEncodeTiled", (void**)&encode_fn,
                            cudaEnableDefault);
#endif

    void *pA = nullptr, *pW = nullptr;
    cudaGetSymbolAddress(&pA, g_Ah);
    cudaGetSymbolAddress(&pW, g_Wh);

    static CUtensorMap tmA, tmW;    // deterministic rebuild every call
    encode_map(encode_fn, &tmA, pA, TOKENS);
    encode_map(encode_fn, &tmW, pW, OUTF);

    cudaFuncSetAttribute(gemm_kernel, cudaFuncAttributeMaxDynamicSharedMemorySize, SMEM_TOTAL);

    detect_wfmt_kernel<<<1, 256>>>(w);
    detect_kernel<<<1, 256>>>(small0, small1);

    size_t n_w = (size_t)OUTF * INF / 8;
    convert_w_kernel<<<(unsigned)(n_w / 256), 256>>>(w);
    size_t n_a = (size_t)TOKENS * INF / 8;
    convert_a_kernel<<<(unsigned)(n_a / 256), 256>>>(inp);

    gemm_kernel<<<8192, 256, SMEM_TOTAL>>>(out, small0, small1, tmA, tmW);
}